// round 12
// baseline (speedup 1.0000x reference)
#include <cuda_runtime.h>
#include <cuda_fp16.h>
#include <math.h>

#define NPTS   8192
#define MPTS   8192
#define NB     16
#define WIDTH  32
#define NSPLIT 19
#define MAXJ   432   // ceil(8192/19)
#define IBLK   256
#define REC    16    // x,y,z,cut | w_h2,bp0,bp1,bp2 | bp3..bp6 | bp7,pad,pad,pad
#define NBINS  32768 // 32^3 Morton bins

__device__ float g_packed[NPTS * REC];
__device__ __align__(16) float g_heg[NB];
__device__ float g_partial[(size_t)NSPLIT * MPTS * NB];
__device__ int   g_hist[NBINS];
__device__ int   g_binstart[NBINS];
__device__ int   g_bincur[NBINS];
__device__ int   g_obin[MPTS];
__device__ int   g_operm[MPTS];   // slot -> original output index

// ---- raw MUFU helpers ----
__device__ __forceinline__ float f_ex2(float x) {
    float r; asm("ex2.approx.f32 %0, %1;" : "=f"(r) : "f"(x)); return r;
}
__device__ __forceinline__ float f_lg2(float x) {
    float r; asm("lg2.approx.f32 %0, %1;" : "=f"(r) : "f"(x)); return r;
}
__device__ __forceinline__ float f_rcp(float x) {
    float r; asm("rcp.approx.f32 %0, %1;" : "=f"(r) : "f"(x)); return r;
}
__device__ __forceinline__ float fast_tanh(float a) {
    float u = f_ex2(2.885390081777927f * a);
    return fmaf(-2.0f, f_rcp(u + 1.0f), 1.0f);
}
__device__ __forceinline__ float fast_log_cosh(float t) {
    const float LN2 = 0.69314718055994531f;
    float a = fabsf(t);
    float v = f_ex2(-2.885390081777927f * a);
    return fmaf(f_lg2(1.0f + v), LN2, a - LN2);
}
__device__ __forceinline__ unsigned h2ex2_raw(unsigned x) {
    unsigned r;
    asm("ex2.approx.f16x2 %0, %1;" : "=r"(r) : "r"(x));
    return r;
}

__global__ void zero_kernel() {
    int i = blockIdx.x * blockDim.x + threadIdx.x;
    if (i < NBINS) g_hist[i] = 0;
}

// Warp-per-point setup. Adds per-j skip cutoff: all 16 half-exps are exactly
// zero when d2 >= 23/|bp|_min (half flushes ex2(arg<=-25) to +0).
__global__ void __launch_bounds__(256)
setup_kernel(const float* __restrict__ rho,
             const float* __restrict__ gamma,
             const float* __restrict__ coords,
             const float* __restrict__ weights,
             const float* __restrict__ w1,
             const float* __restrict__ b1,
             const float* __restrict__ w2,
             const float* __restrict__ b2) {
    __shared__ float s_w2[WIDTH * NB];
    int tid = threadIdx.x;
    for (int v = tid; v < WIDTH * NB; v += blockDim.x) s_w2[v] = w2[v];
    __syncthreads();

    int lane = tid & 31;
    int warp = tid >> 5;
    int j = blockIdx.x * (blockDim.x >> 5) + warp;
    if (j >= NPTS) return;

    const float C     = 38.283120002509214f;
    const float LOG2E = 1.44269504088896340f;
    const float LN2   = 0.69314718055994531f;

    float r = rho[j];
    float l = f_lg2(r);
    float r83 = r * r * f_ex2(l * (2.0f / 3.0f));
    float s2 = gamma[j] * f_rcp(C * r83);
    float x = f_lg2(s2 + 1e-4f) * LN2;

    float h = fast_tanh(fmaf(x, w1[lane], b1[lane]));

    int bl = lane & (NB - 1);
    float o0 = b2[bl], o1 = 0.0f;   // 2 accumulators: halve the serial chain
#pragma unroll
    for (int k = 0; k < WIDTH; k += 2) {
        float hk0 = __shfl_sync(0xffffffffu, h, k);
        float hk1 = __shfl_sync(0xffffffffu, h, k + 1);
        o0 = fmaf(hk0, s_w2[k * NB + bl], o0);
        o1 = fmaf(hk1, s_w2[(k + 1) * NB + bl], o1);
    }
    float o = o0 + o1;

    float pref = 3.14159265358979323846f * f_ex2((l - 1.0f) * (2.0f / 3.0f));
    float bp = -pref * fast_log_cosh(o) * LOG2E;

    // warp min of |bp| over the 16 channel lanes
    float ab = (lane < NB) ? fabsf(bp) : 1e30f;
#pragma unroll
    for (int d = 16; d > 0; d >>= 1)
        ab = fminf(ab, __shfl_xor_sync(0xffffffffu, ab, d));
    if (lane == 0)
        g_packed[j * REC + 3] = 23.0f / fmaxf(ab, 1e-20f);   // cut

    // pack channel pairs (2q, 2q+1) into half2 at slots 5..12
    float bpn = __shfl_down_sync(0xffffffffu, bp, 1);
    if (lane < NB && (lane & 1) == 0) {
        __half2 hh = __floats2half2_rn(bp, bpn);
        ((unsigned*)g_packed)[j * REC + 5 + (lane >> 1)] = *(unsigned*)&hh;
    }
    if (lane == 16) g_packed[j * REC + 0] = coords[j * 3 + 0];
    if (lane == 17) g_packed[j * REC + 1] = coords[j * 3 + 1];
    if (lane == 18) g_packed[j * REC + 2] = coords[j * 3 + 2];
    if (lane == 19) {
        __half2 wh = __float2half2_rn(weights[j] * r);
        ((unsigned*)g_packed)[j * REC + 4] = *(unsigned*)&wh;
    }

    if (j == 0) {
        float h0 = fast_tanh(b1[lane]);
        float q0 = b2[bl];
#pragma unroll
        for (int k = 0; k < WIDTH; k++) {
            float hk = __shfl_sync(0xffffffffu, h0, k);
            q0 = fmaf(hk, s_w2[k * NB + bl], q0);
        }
        if (lane < NB) {
            float lc = fast_log_cosh(q0);
            g_heg[lane] = lc * sqrtf(lc);
        }
    }
}

// ---- spatial sort of output points (Morton bins, atomic slots) ----
__device__ __forceinline__ unsigned expand3(unsigned v) {
    v &= 31u;
    v = (v | (v << 8)) & 0x100Fu;
    v = (v | (v << 4)) & 0x10C3u;
    v = (v | (v << 2)) & 0x1249u;
    return v;
}

__global__ void bin_kernel(const float* __restrict__ out_coords) {
    int i = blockIdx.x * blockDim.x + threadIdx.x;
    if (i >= MPTS) return;
    float x = out_coords[i * 3 + 0];
    float y = out_coords[i * 3 + 1];
    float z = out_coords[i * 3 + 2];
    int bx = min(max((int)((x + 20.0f) * 0.8f), 0), 31);
    int by = min(max((int)((y + 20.0f) * 0.8f), 0), 31);
    int bz = min(max((int)((z + 20.0f) * 0.8f), 0), 31);
    unsigned m = expand3(bx) | (expand3(by) << 1) | (expand3(bz) << 2);
    g_obin[i] = (int)m;
    atomicAdd(&g_hist[m], 1);
}

__global__ void __launch_bounds__(1024)
scan_kernel() {
    __shared__ int sa[1024], sb[1024];
    int t = threadIdx.x;
    int base = t * 32;
    int loc[32];
    int tot = 0;
#pragma unroll
    for (int k = 0; k < 32; k++) { loc[k] = tot; tot += g_hist[base + k]; }
    sa[t] = tot;
    __syncthreads();
    int* src = sa; int* dst = sb;
    for (int d = 1; d < 1024; d <<= 1) {
        dst[t] = src[t] + ((t >= d) ? src[t - d] : 0);
        __syncthreads();
        int* tmp = src; src = dst; dst = tmp;
    }
    int excl = src[t] - tot;
#pragma unroll
    for (int k = 0; k < 32; k++) {
        g_binstart[base + k] = excl + loc[k];
        g_bincur[base + k] = excl + loc[k];
    }
}

// slot order within a bin is atomic (non-deterministic) but per-point output
// values are slot-independent (per-lane predication in main).
__global__ void slot_kernel() {
    int i = blockIdx.x * blockDim.x + threadIdx.x;
    if (i >= MPTS) return;
    int slot = atomicAdd(&g_bincur[g_obin[i]], 1);
    g_operm[slot] = i;
}

// Grid (32,19)=608=152x4 (balanced). One tile per split. Per-j early-out:
// if d2 >= cut every half-exp is exactly +0, so skipping is bit-identical.
__global__ void __launch_bounds__(IBLK, 4)
main_kernel(const float* __restrict__ out_coords) {
    __shared__ float tile[MAXJ * REC];   // 27.6 KB

    int ilin = blockIdx.x * IBLK + threadIdx.x;
    int i = g_operm[ilin];
    int split = blockIdx.y;

    float ox = out_coords[i * 3 + 0];
    float oy = out_coords[i * 3 + 1];
    float oz = out_coords[i * 3 + 2];

    int jbeg = (split * NPTS) / NSPLIT;
    int jend = ((split + 1) * NPTS) / NSPLIT;
    int cnt = jend - jbeg;

    {
        const float4* src = (const float4*)(g_packed + (size_t)jbeg * REC);
        float4* dst = (float4*)tile;
        int nvec = cnt * (REC / 4);
        for (int v = threadIdx.x; v < nvec; v += IBLK) dst[v] = src[v];
    }
    __syncthreads();

    float acc[NB];
#pragma unroll
    for (int b = 0; b < NB; b++) acc[b] = 0.0f;

    for (int j0 = 0; j0 < cnt; j0 += 16) {
        int jn = min(16, cnt - j0);
        __half2 hacc[8];
#pragma unroll
        for (int q = 0; q < 8; q++) hacc[q] = __float2half2_rn(0.0f);

        for (int jt = j0; jt < j0 + jn; ++jt) {
            const float* p = tile + jt * REC;
            float4 cw = *(const float4*)p;   // x, y, z, cut
            float dx = ox - cw.x;
            float dy = oy - cw.y;
            float dz = oz - cw.z;
            float d2 = fmaf(dx, dx, fmaf(dy, dy, dz * dz));
            if (d2 < cw.w) {                 // else: all 16 exps == +0 exactly
                __half2 d2h = __float2half2_rn(d2);
                unsigned wu = ((const unsigned*)p)[4];
                __half2 wh = *(__half2*)&wu;
                const __half2* bp = (const __half2*)(p + 5);
#pragma unroll
                for (int q = 0; q < 8; q++) {
                    __half2 arg = __hmul2(bp[q], d2h);
                    unsigned eu = h2ex2_raw(*(unsigned*)&arg);
                    hacc[q] = __hfma2(*(__half2*)&eu, wh, hacc[q]);
                }
            }
        }
#pragma unroll
        for (int q = 0; q < 8; q++) {
            float2 f = __half22float2(hacc[q]);
            acc[2 * q + 0] += f.x;
            acc[2 * q + 1] += f.y;
        }
    }

    float* outp = g_partial + ((size_t)split * MPTS + ilin) * NB;
#pragma unroll
    for (int b = 0; b < NB; b++) outp[b] = acc[b];
}

// Vectorized reduce with scatter back to original output order.
__global__ void reduce_kernel(float* __restrict__ out) {
    int t = blockIdx.x * blockDim.x + threadIdx.x;   // 0 .. MPTS*NB/4-1
    if (t >= MPTS * NB / 4) return;
    int ilin = t >> 2;
    int c4 = (t & 3);
    float4 s = make_float4(0.0f, 0.0f, 0.0f, 0.0f);
    const float4* part4 = (const float4*)g_partial;
    const int stride = MPTS * NB / 4;
#pragma unroll
    for (int sp = 0; sp < NSPLIT; sp++) {
        float4 v = part4[(size_t)sp * stride + t];
        s.x += v.x; s.y += v.y; s.z += v.z; s.w += v.w;
    }
    float4 hg = ((const float4*)g_heg)[c4];
    s.x *= hg.x; s.y *= hg.y; s.z *= hg.z; s.w *= hg.w;
    int io = g_operm[ilin];
    ((float4*)out)[io * 4 + c4] = s;
}

extern "C" void kernel_launch(void* const* d_in, const int* in_sizes, int n_in,
                              void* d_out, int out_size) {
    const float* rho        = (const float*)d_in[0];
    const float* gamma      = (const float*)d_in[1];
    const float* coords     = (const float*)d_in[2];
    const float* weights    = (const float*)d_in[3];
    const float* out_coords = (const float*)d_in[4];
    const float* w1         = (const float*)d_in[5];
    const float* b1         = (const float*)d_in[6];
    const float* w2         = (const float*)d_in[7];
    const float* b2         = (const float*)d_in[8];

    zero_kernel<<<NBINS / 256, 256>>>();
    setup_kernel<<<NPTS / 8, 256>>>(rho, gamma, coords, weights,
                                    w1, b1, w2, b2);
    bin_kernel<<<MPTS / 256, 256>>>(out_coords);
    scan_kernel<<<1, 1024>>>();
    slot_kernel<<<MPTS / 256, 256>>>();
    dim3 grid(MPTS / IBLK, NSPLIT);
    main_kernel<<<grid, IBLK>>>(out_coords);
    reduce_kernel<<<(MPTS * NB / 4 + 255) / 256, 256>>>((float*)d_out);
}

// round 13
// speedup vs baseline: 2.3454x; 2.3454x over previous
#include <cuda_runtime.h>
#include <cuda_fp16.h>
#include <math.h>

#define NPTS   8192
#define MPTS   8192
#define NB     16
#define WIDTH  32
#define NSPLIT 19
#define MAXJ   432   // ceil(8192/19)
#define IBLK   256
#define REC    12    // x, y, z, w_h2(u32), bp_h2[8](u32)

__device__ float g_packed[NPTS * REC];
__device__ __align__(16) float g_heg[NB];
__device__ float g_partial[(size_t)NSPLIT * MPTS * NB];
__device__ int   g_cnt[MPTS / IBLK];   // per-i-column tickets (zero-init)

// ---- raw MUFU helpers ----
__device__ __forceinline__ float f_ex2(float x) {
    float r; asm("ex2.approx.f32 %0, %1;" : "=f"(r) : "f"(x)); return r;
}
__device__ __forceinline__ float f_lg2(float x) {
    float r; asm("lg2.approx.f32 %0, %1;" : "=f"(r) : "f"(x)); return r;
}
__device__ __forceinline__ float f_rcp(float x) {
    float r; asm("rcp.approx.f32 %0, %1;" : "=f"(r) : "f"(x)); return r;
}
__device__ __forceinline__ float fast_tanh(float a) {
    float u = f_ex2(2.885390081777927f * a);   // exp(2a)
    return fmaf(-2.0f, f_rcp(u + 1.0f), 1.0f);
}
__device__ __forceinline__ float fast_log_cosh(float t) {
    const float LN2 = 0.69314718055994531f;
    float a = fabsf(t);
    float v = f_ex2(-2.885390081777927f * a);  // exp(-2a)
    return fmaf(f_lg2(1.0f + v), LN2, a - LN2);
}

// Guaranteed single-op f16x2 exp2 on MUFU (two values per MUFU slot).
__device__ __forceinline__ unsigned h2ex2_raw(unsigned x) {
    unsigned r;
    asm("ex2.approx.f16x2 %0, %1;" : "=r"(r) : "r"(x));
    return r;
}

// Warp-per-point setup: lane k owns hidden unit k; WIDTH->NB layer via
// 32 SHFL broadcasts (2 accumulators to halve the serial chain); lane b<16
// owns basis b. Packs bp into half2 pairs.
__global__ void __launch_bounds__(256)
setup_kernel(const float* __restrict__ rho,
             const float* __restrict__ gamma,
             const float* __restrict__ coords,
             const float* __restrict__ weights,
             const float* __restrict__ w1,
             const float* __restrict__ b1,
             const float* __restrict__ w2,
             const float* __restrict__ b2) {
    __shared__ float s_w2[WIDTH * NB];
    int tid = threadIdx.x;
    for (int v = tid; v < WIDTH * NB; v += blockDim.x) s_w2[v] = w2[v];
    __syncthreads();

    int lane = tid & 31;
    int warp = tid >> 5;
    int j = blockIdx.x * (blockDim.x >> 5) + warp;
    if (j >= NPTS) return;

    const float C     = 38.283120002509214f;   // 4*(3*pi^2)^(2/3)
    const float LOG2E = 1.44269504088896340f;
    const float LN2   = 0.69314718055994531f;

    float r = rho[j];
    float l = f_lg2(r);
    float r83 = r * r * f_ex2(l * (2.0f / 3.0f));          // r^(8/3)
    float s2 = gamma[j] * f_rcp(C * r83);
    float x = f_lg2(s2 + 1e-4f) * LN2;                     // log(s2+eps)

    float h = fast_tanh(fmaf(x, w1[lane], b1[lane]));

    int bl = lane & (NB - 1);
    float o0 = b2[bl], o1 = 0.0f;
#pragma unroll
    for (int k = 0; k < WIDTH; k += 2) {
        float hk0 = __shfl_sync(0xffffffffu, h, k);
        float hk1 = __shfl_sync(0xffffffffu, h, k + 1);
        o0 = fmaf(hk0, s_w2[k * NB + bl], o0);
        o1 = fmaf(hk1, s_w2[(k + 1) * NB + bl], o1);
    }
    float o = o0 + o1;

    float pref = 3.14159265358979323846f * f_ex2((l - 1.0f) * (2.0f / 3.0f));
    float bp = -pref * fast_log_cosh(o) * LOG2E;

    // pack channel pairs (2q, 2q+1) into half2
    float bpn = __shfl_down_sync(0xffffffffu, bp, 1);
    if (lane < NB && (lane & 1) == 0) {
        __half2 hh = __floats2half2_rn(bp, bpn);
        ((unsigned*)g_packed)[j * REC + 4 + (lane >> 1)] = *(unsigned*)&hh;
    }
    if (lane == 16) g_packed[j * REC + 0] = coords[j * 3 + 0];
    if (lane == 17) g_packed[j * REC + 1] = coords[j * 3 + 1];
    if (lane == 18) g_packed[j * REC + 2] = coords[j * 3 + 2];
    if (lane == 19) {
        __half2 wh = __float2half2_rn(weights[j] * r);
        ((unsigned*)g_packed)[j * REC + 3] = *(unsigned*)&wh;
    }

    if (j == 0) {
        float h0 = fast_tanh(b1[lane]);
        float q0 = b2[bl];
#pragma unroll
        for (int k = 0; k < WIDTH; k++) {
            float hk = __shfl_sync(0xffffffffu, h0, k);
            q0 = fmaf(hk, s_w2[k * NB + bl], q0);
        }
        if (lane < NB) {
            float lc = fast_log_cosh(q0);
            g_heg[lane] = lc * sqrtf(lc);                  // lc^1.5
        }
    }
}

// Grid (32, 19) = 608 blocks = 152 SMs x 4: perfectly balanced on GB300.
// One smem tile per split; branch-free straight-line inner loop (pipelined).
// The 19th block to finish an i-column reduces it in place (ticket pattern:
// atomics gate only WHO reduces; the sum order sp=0..18 is fixed ->
// bit-identical to the separate reduce kernel, fully deterministic).
__global__ void __launch_bounds__(IBLK)
main_kernel(const float* __restrict__ out_coords, float4* __restrict__ out4) {
    __shared__ float tile[MAXJ * REC];   // 20.7 KB
    __shared__ int s_old;

    int i = blockIdx.x * IBLK + threadIdx.x;
    int split = blockIdx.y;

    float ox = out_coords[i * 3 + 0];
    float oy = out_coords[i * 3 + 1];
    float oz = out_coords[i * 3 + 2];

    int jbeg = (split * NPTS) / NSPLIT;
    int jend = ((split + 1) * NPTS) / NSPLIT;
    int cnt = jend - jbeg;

    {
        const float4* src = (const float4*)(g_packed + (size_t)jbeg * REC);
        float4* dst = (float4*)tile;
        int nvec = cnt * (REC / 4);   // 3 float4 per j
        for (int v = threadIdx.x; v < nvec; v += IBLK) dst[v] = src[v];
    }
    __syncthreads();

    float acc[NB];
#pragma unroll
    for (int b = 0; b < NB; b++) acc[b] = 0.0f;

    for (int j0 = 0; j0 < cnt; j0 += 16) {
        int jn = min(16, cnt - j0);
        // half2 partial accumulators (<=16 terms, each <=0.2: no overflow)
        __half2 hacc[8];
#pragma unroll
        for (int q = 0; q < 8; q++) hacc[q] = __float2half2_rn(0.0f);

        for (int jt = j0; jt < j0 + jn; ++jt) {
            const float* p = tile + jt * REC;
            float4 cw = *(const float4*)p;   // x, y, z, w_h2(bits)
            float dx = ox - cw.x;
            float dy = oy - cw.y;
            float dz = oz - cw.z;
            float d2 = fmaf(dx, dx, fmaf(dy, dy, dz * dz));
            __half2 d2h = __float2half2_rn(d2);      // one F2FP pack
            __half2 wh = *(__half2*)&cw.w;
            const __half2* bp = (const __half2*)(p + 4);
#pragma unroll
            for (int q = 0; q < 8; q++) {
                __half2 arg = __hmul2(bp[q], d2h);   // HMUL2 (fma pipe)
                unsigned eu = h2ex2_raw(*(unsigned*)&arg); // 1 MUFU slot, 2 exps
                hacc[q] = __hfma2(*(__half2*)&eu, wh, hacc[q]);
            }
        }
        // flush to f32
#pragma unroll
        for (int q = 0; q < 8; q++) {
            float2 f = __half22float2(hacc[q]);
            acc[2 * q + 0] += f.x;
            acc[2 * q + 1] += f.y;
        }
    }

    float* outp = g_partial + ((size_t)split * MPTS + i) * NB;
#pragma unroll
    for (int b = 0; b < NB; b++) outp[b] = acc[b];

    // ---- fused deterministic reduction (last-arriver ticket) ----
    __syncthreads();
    if (threadIdx.x == 0) {
        __threadfence();                       // publish partials
        s_old = atomicAdd(&g_cnt[blockIdx.x], 1);
    }
    __syncthreads();
    if (s_old == NSPLIT - 1) {
        __threadfence();                       // acquire others' partials
        const float4* part4 = (const float4*)g_partial;
        const int stride = MPTS * NB / 4;
#pragma unroll
        for (int c4 = 0; c4 < 4; c4++) {
            int t = i * 4 + c4;
            float4 s = make_float4(0.0f, 0.0f, 0.0f, 0.0f);
#pragma unroll
            for (int sp = 0; sp < NSPLIT; sp++) {
                float4 v = part4[(size_t)sp * stride + t];
                s.x += v.x; s.y += v.y; s.z += v.z; s.w += v.w;
            }
            float4 hg = ((const float4*)g_heg)[c4];
            s.x *= hg.x; s.y *= hg.y; s.z *= hg.z; s.w *= hg.w;
            out4[t] = s;
        }
        if (threadIdx.x == 0) g_cnt[blockIdx.x] = 0;   // reset for replay
    }
}

extern "C" void kernel_launch(void* const* d_in, const int* in_sizes, int n_in,
                              void* d_out, int out_size) {
    const float* rho        = (const float*)d_in[0];
    const float* gamma      = (const float*)d_in[1];
    const float* coords     = (const float*)d_in[2];
    const float* weights    = (const float*)d_in[3];
    const float* out_coords = (const float*)d_in[4];
    const float* w1         = (const float*)d_in[5];
    const float* b1         = (const float*)d_in[6];
    const float* w2         = (const float*)d_in[7];
    const float* b2         = (const float*)d_in[8];

    setup_kernel<<<NPTS / 8, 256>>>(rho, gamma, coords, weights,
                                    w1, b1, w2, b2);
    dim3 grid(MPTS / IBLK, NSPLIT);
    main_kernel<<<grid, IBLK>>>(out_coords, (float4*)d_out);
}

// round 14
// speedup vs baseline: 2.5267x; 1.0773x over previous
#include <cuda_runtime.h>
#include <cuda_fp16.h>
#include <math.h>

#define NPTS   8192
#define MPTS   8192
#define NB     16
#define WIDTH  32
#define NSPLIT 19
#define MAXJ   432   // ceil(8192/19) = 432 = 27*16 exactly
#define IBLK   256
#define REC    12    // x, y, z, w_h2(u32), bp_h2[8](u32)

__device__ float g_packed[NPTS * REC];
__device__ __align__(16) float g_heg[NB];
__device__ float g_partial[(size_t)NSPLIT * MPTS * NB];

// ---- raw MUFU helpers ----
__device__ __forceinline__ float f_ex2(float x) {
    float r; asm("ex2.approx.f32 %0, %1;" : "=f"(r) : "f"(x)); return r;
}
__device__ __forceinline__ float f_lg2(float x) {
    float r; asm("lg2.approx.f32 %0, %1;" : "=f"(r) : "f"(x)); return r;
}
__device__ __forceinline__ float f_rcp(float x) {
    float r; asm("rcp.approx.f32 %0, %1;" : "=f"(r) : "f"(x)); return r;
}
__device__ __forceinline__ float fast_tanh(float a) {
    float u = f_ex2(2.885390081777927f * a);   // exp(2a)
    return fmaf(-2.0f, f_rcp(u + 1.0f), 1.0f);
}
__device__ __forceinline__ float fast_log_cosh(float t) {
    const float LN2 = 0.69314718055994531f;
    float a = fabsf(t);
    float v = f_ex2(-2.885390081777927f * a);  // exp(-2a)
    return fmaf(f_lg2(1.0f + v), LN2, a - LN2);
}

// Guaranteed single-op f16x2 exp2 on MUFU (two values per MUFU slot).
__device__ __forceinline__ unsigned h2ex2_raw(unsigned x) {
    unsigned r;
    asm("ex2.approx.f16x2 %0, %1;" : "=r"(r) : "r"(x));
    return r;
}

// Warp-per-point setup: lane k owns hidden unit k; WIDTH->NB layer via
// 32 SHFL broadcasts (2 accumulators halve the serial chain); lane b<16
// owns basis b. Packs bp into half2 pairs.
__global__ void __launch_bounds__(256)
setup_kernel(const float* __restrict__ rho,
             const float* __restrict__ gamma,
             const float* __restrict__ coords,
             const float* __restrict__ weights,
             const float* __restrict__ w1,
             const float* __restrict__ b1,
             const float* __restrict__ w2,
             const float* __restrict__ b2) {
    __shared__ float s_w2[WIDTH * NB];
    int tid = threadIdx.x;
    for (int v = tid; v < WIDTH * NB; v += blockDim.x) s_w2[v] = w2[v];
    __syncthreads();

    int lane = tid & 31;
    int warp = tid >> 5;
    int j = blockIdx.x * (blockDim.x >> 5) + warp;
    if (j >= NPTS) return;

    const float C     = 38.283120002509214f;   // 4*(3*pi^2)^(2/3)
    const float LOG2E = 1.44269504088896340f;
    const float LN2   = 0.69314718055994531f;

    float r = rho[j];
    float l = f_lg2(r);
    float r83 = r * r * f_ex2(l * (2.0f / 3.0f));          // r^(8/3)
    float s2 = gamma[j] * f_rcp(C * r83);
    float x = f_lg2(s2 + 1e-4f) * LN2;                     // log(s2+eps)

    float h = fast_tanh(fmaf(x, w1[lane], b1[lane]));

    int bl = lane & (NB - 1);
    float o0 = b2[bl], o1 = 0.0f;
#pragma unroll
    for (int k = 0; k < WIDTH; k += 2) {
        float hk0 = __shfl_sync(0xffffffffu, h, k);
        float hk1 = __shfl_sync(0xffffffffu, h, k + 1);
        o0 = fmaf(hk0, s_w2[k * NB + bl], o0);
        o1 = fmaf(hk1, s_w2[(k + 1) * NB + bl], o1);
    }
    float o = o0 + o1;

    float pref = 3.14159265358979323846f * f_ex2((l - 1.0f) * (2.0f / 3.0f));
    float bp = -pref * fast_log_cosh(o) * LOG2E;

    // pack channel pairs (2q, 2q+1) into half2
    float bpn = __shfl_down_sync(0xffffffffu, bp, 1);
    if (lane < NB && (lane & 1) == 0) {
        __half2 hh = __floats2half2_rn(bp, bpn);
        ((unsigned*)g_packed)[j * REC + 4 + (lane >> 1)] = *(unsigned*)&hh;
    }
    if (lane == 16) g_packed[j * REC + 0] = coords[j * 3 + 0];
    if (lane == 17) g_packed[j * REC + 1] = coords[j * 3 + 1];
    if (lane == 18) g_packed[j * REC + 2] = coords[j * 3 + 2];
    if (lane == 19) {
        __half2 wh = __float2half2_rn(weights[j] * r);
        ((unsigned*)g_packed)[j * REC + 3] = *(unsigned*)&wh;
    }

    if (j == 0) {
        float h0 = fast_tanh(b1[lane]);
        float q0 = b2[bl];
#pragma unroll
        for (int k = 0; k < WIDTH; k++) {
            float hk = __shfl_sync(0xffffffffu, h0, k);
            q0 = fmaf(hk, s_w2[k * NB + bl], q0);
        }
        if (lane < NB) {
            float lc = fast_log_cosh(q0);
            g_heg[lane] = lc * sqrtf(lc);                  // lc^1.5
        }
    }
}

// Grid (32, 19) = 608 blocks = 152 SMs x 4: perfectly balanced on GB300.
// Tile zero-padded to exactly MAXJ=432=27*16 records: the j-nest has
// constant trip counts (27 x 16), branch-free straight-line body.
// Zero records contribute exactly +0 (w=0), so padding is bit-identical.
__global__ void __launch_bounds__(IBLK)
main_kernel(const float* __restrict__ out_coords) {
    __shared__ float tile[MAXJ * REC];   // 20.7 KB

    int i = blockIdx.x * IBLK + threadIdx.x;
    int split = blockIdx.y;

    float ox = out_coords[i * 3 + 0];
    float oy = out_coords[i * 3 + 1];
    float oz = out_coords[i * 3 + 2];

    int jbeg = (split * NPTS) / NSPLIT;
    int jend = ((split + 1) * NPTS) / NSPLIT;
    int cnt = jend - jbeg;

    {
        const float4* src = (const float4*)(g_packed + (size_t)jbeg * REC);
        float4* dst = (float4*)tile;
        int nvec = cnt * (REC / 4);            // 3 float4 per j
        const int nvec_pad = MAXJ * (REC / 4); // fill remainder with zeros
        for (int v = threadIdx.x; v < nvec_pad; v += IBLK)
            dst[v] = (v < nvec) ? src[v]
                                : make_float4(0.0f, 0.0f, 0.0f, 0.0f);
    }
    __syncthreads();

    float acc[NB];
#pragma unroll
    for (int b = 0; b < NB; b++) acc[b] = 0.0f;

#pragma unroll 1
    for (int j0 = 0; j0 < MAXJ; j0 += 16) {
        // half2 partial accumulators (16 terms, each <=0.2: no overflow)
        __half2 hacc[8];
#pragma unroll
        for (int q = 0; q < 8; q++) hacc[q] = __float2half2_rn(0.0f);

#pragma unroll
        for (int jt = j0; jt < j0 + 16; ++jt) {
            const float* p = tile + jt * REC;
            float4 cw = *(const float4*)p;   // x, y, z, w_h2(bits)
            float dx = ox - cw.x;
            float dy = oy - cw.y;
            float dz = oz - cw.z;
            float d2 = fmaf(dx, dx, fmaf(dy, dy, dz * dz));
            __half2 d2h = __float2half2_rn(d2);      // one F2FP pack
            __half2 wh = *(__half2*)&cw.w;
            const __half2* bp = (const __half2*)(p + 4);
#pragma unroll
            for (int q = 0; q < 8; q++) {
                __half2 arg = __hmul2(bp[q], d2h);   // HMUL2 (fma pipe)
                unsigned eu = h2ex2_raw(*(unsigned*)&arg); // 1 MUFU, 2 exps
                hacc[q] = __hfma2(*(__half2*)&eu, wh, hacc[q]);
            }
        }
        // flush to f32
#pragma unroll
        for (int q = 0; q < 8; q++) {
            float2 f = __half22float2(hacc[q]);
            acc[2 * q + 0] += f.x;
            acc[2 * q + 1] += f.y;
        }
    }

    float* outp = g_partial + ((size_t)split * MPTS + i) * NB;
#pragma unroll
    for (int b = 0; b < NB; b++) outp[b] = acc[b];
}

// Vectorized reduce: one thread per 4 outputs, float4 loads across splits.
__global__ void reduce_kernel(float4* __restrict__ out4) {
    int t = blockIdx.x * blockDim.x + threadIdx.x;   // 0 .. MPTS*NB/4-1
    if (t >= MPTS * NB / 4) return;
    float4 s = make_float4(0.0f, 0.0f, 0.0f, 0.0f);
    const float4* part4 = (const float4*)g_partial;
    const int stride = MPTS * NB / 4;
#pragma unroll
    for (int sp = 0; sp < NSPLIT; sp++) {
        float4 v = part4[(size_t)sp * stride + t];
        s.x += v.x; s.y += v.y; s.z += v.z; s.w += v.w;
    }
    float4 hg = ((const float4*)g_heg)[t & 3];   // 4 consecutive channels
    s.x *= hg.x; s.y *= hg.y; s.z *= hg.z; s.w *= hg.w;
    out4[t] = s;
}

extern "C" void kernel_launch(void* const* d_in, const int* in_sizes, int n_in,
                              void* d_out, int out_size) {
    const float* rho        = (const float*)d_in[0];
    const float* gamma      = (const float*)d_in[1];
    const float* coords     = (const float*)d_in[2];
    const float* weights    = (const float*)d_in[3];
    const float* out_coords = (const float*)d_in[4];
    const float* w1         = (const float*)d_in[5];
    const float* b1         = (const float*)d_in[6];
    const float* w2         = (const float*)d_in[7];
    const float* b2         = (const float*)d_in[8];

    setup_kernel<<<NPTS / 8, 256>>>(rho, gamma, coords, weights,
                                    w1, b1, w2, b2);
    dim3 grid(MPTS / IBLK, NSPLIT);
    main_kernel<<<grid, IBLK>>>(out_coords);
    reduce_kernel<<<(MPTS * NB / 4 + 255) / 256, 256>>>((float4*)d_out);
}